// round 13
// baseline (speedup 1.0000x reference)
#include <cuda_runtime.h>
#include <cuda_fp16.h>
#include <math.h>
#include <stdint.h>

// Problem constants
#define D     1024
#define H_    16
#define HD    64
#define FF    4096
#define NB    2
#define LQ    2048
#define MROWS (NB * LQ)   // 4096
#define EPS   1e-5f

// ---------------------------------------------------------------------------
// Scratch (device globals — no allocation allowed)
// ---------------------------------------------------------------------------
__device__ float g_proj[MROWS * D];       // fp32 id 0
__device__ float g_h   [MROWS * D];       // fp32 id 1
__device__ float g_ff2 [MROWS * D];       // fp32 id 2

__device__ __half g_x16   [MROWS * D];    // h id 0
__device__ __half g_attn16[MROWS * D];    // h id 1
__device__ __half g_h16   [MROWS * D];    // h id 2
__device__ __half g_ff116 [MROWS * FF];   // h id 3
__device__ __half g_wqkvT16[3 * D * D];   // h id 4
__device__ __half g_woT16 [D * D];        // h id 5
__device__ __half g_w1T16 [FF * D];       // h id 6
__device__ __half g_w2T16 [D * FF];       // h id 7
__device__ __half g_qkv16 [MROWS * 3 * D];// h id 8

__device__ __forceinline__ float* scratch(int id) {
    switch (id) {
        case 0:  return g_proj;
        case 1:  return g_h;
        default: return g_ff2;
    }
}
__device__ __forceinline__ __half* scratch_h(int id) {
    switch (id) {
        case 0:  return g_x16;
        case 1:  return g_attn16;
        case 2:  return g_h16;
        case 3:  return g_ff116;
        case 4:  return g_wqkvT16;
        case 5:  return g_woT16;
        case 6:  return g_w1T16;
        case 7:  return g_w2T16;
        default: return g_qkv16;
    }
}

// ---------------------------------------------------------------------------
// mma / async helpers (base sm_103 target OK)
// ---------------------------------------------------------------------------
__device__ __forceinline__ void mma_f16(float* c, const uint32_t* a, const uint32_t* b) {
    asm volatile(
        "mma.sync.aligned.m16n8k16.row.col.f32.f16.f16.f32 "
        "{%0,%1,%2,%3}, {%4,%5,%6,%7}, {%8,%9}, {%0,%1,%2,%3};"
        : "+f"(c[0]), "+f"(c[1]), "+f"(c[2]), "+f"(c[3])
        : "r"(a[0]), "r"(a[1]), "r"(a[2]), "r"(a[3]),
          "r"(b[0]), "r"(b[1]));
}

__device__ __forceinline__ uint32_t packh2(float a, float b) {
    __half2 h = __floats2half2_rn(a, b);
    return *(uint32_t*)&h;
}

__device__ __forceinline__ void cp_async16(uint32_t dst, const void* src) {
    asm volatile("cp.async.cg.shared.global [%0], [%1], 16;" :: "r"(dst), "l"(src));
}
__device__ __forceinline__ void cp_commit() {
    asm volatile("cp.async.commit_group;" ::: "memory");
}
__device__ __forceinline__ void cp_wait2() {
    asm volatile("cp.async.wait_group 2;" ::: "memory");
}
__device__ __forceinline__ void cp_wait0() {
    asm volatile("cp.async.wait_group 0;" ::: "memory");
}

#define LDSM4(r0, r1, r2, r3, addr) \
    asm volatile("ldmatrix.sync.aligned.m8n8.x4.shared.b16 {%0,%1,%2,%3}, [%4];" \
                 : "=r"(r0), "=r"(r1), "=r"(r2), "=r"(r3) : "r"(addr))

#define LDSM4T(r0, r1, r2, r3, addr) \
    asm volatile("ldmatrix.sync.aligned.m8n8.x4.trans.shared.b16 {%0,%1,%2,%3}, [%4];" \
                 : "=r"(r0), "=r"(r1), "=r"(r2), "=r"(r3) : "r"(addr))

// 64B-row XOR swizzle (GEMM stages): 16B segment for (row, chunk c in 0..3)
__device__ __forceinline__ int phys16(int row, int c) {
    return (row >> 1) * 8 + ((((row & 1) << 2) | c) ^ ((row >> 1) & 3));
}
// 128B-row XOR swizzle (attention tiles): seg for (row, seg-col c in 0..7)
#define ATT_SEG(row, c) (((row) * 8) + ((c) ^ ((row) & 7)))

// ---------------------------------------------------------------------------
// fp32 -> fp16 convert (x)
// ---------------------------------------------------------------------------
__global__ __launch_bounds__(256)
void cvt16_k(const float* __restrict__ src, int dstId)
{
    uint32_t* d = (uint32_t*)scratch_h(dstId);
    const int i = blockIdx.x * 256 + threadIdx.x;
    const float4 v = ((const float4*)src)[i];
    d[i * 2 + 0] = packh2(v.x, v.y);
    d[i * 2 + 1] = packh2(v.z, v.w);
}

// ---------------------------------------------------------------------------
// Weight transpose -> fp16: dst[c][r] = half(src[r][c])
// ---------------------------------------------------------------------------
__global__ __launch_bounds__(256)
void transpose_k(const float* __restrict__ src, int dstId, int R, int C)
{
    __shared__ float t[32][33];
    __half* dst = scratch_h(dstId);
    const int bx = blockIdx.x * 32;
    const int by = blockIdx.y * 32;
    const int tx = threadIdx.x & 31;
    const int ty = threadIdx.x >> 5;
    #pragma unroll
    for (int i = 0; i < 32; i += 8)
        t[ty + i][tx] = src[(size_t)(by + ty + i) * C + bx + tx];
    __syncthreads();
    #pragma unroll
    for (int i = 0; i < 32; i += 8)
        dst[(size_t)(bx + ty + i) * R + by + tx] = __float2half(t[tx][ty + i]);
}

// ---------------------------------------------------------------------------
// FP16 GEMM 128x128 (R10 layout), 6-stage cp.async, TWO chunks per barrier.
// 8 warps of 64x32, BK=32. C = A @ Bt^T + bias (opt ReLU / fp16 out).
// ---------------------------------------------------------------------------
#define STAGE_B 16384
#define NSTAGE  6
#define GEMM_SMEM (NSTAGE * STAGE_B)   // 98304

__global__ __launch_bounds__(256)
void gemm_f16(int Aid, int Bid, const float* __restrict__ bias,
              int Cid, int outHalf, int M, int N, int K, int relu)
{
    extern __shared__ char smem[];
    const uint32_t smem_u = (uint32_t)__cvta_generic_to_shared(smem);

    const __half* A  = scratch_h(Aid);
    const __half* Bt = scratch_h(Bid);

    const int tid  = threadIdx.x;
    const int wid  = tid >> 5;
    const int lane = tid & 31;
    const int gid  = lane >> 2;
    const int tig  = lane & 3;
    const int warpM = (wid & 1) * 64;
    const int warpN = (wid >> 1) * 32;
    const int m0 = blockIdx.y * 128;
    const int n0 = blockIdx.x * 128;

    uint32_t ld_dst[4];
    const __half* ld_src[4];
    #pragma unroll
    for (int j = 0; j < 4; j++) {
        const int s   = j * 256 + tid;
        const int isB = s >= 512;
        const int ss  = s & 511;
        const int row = ss >> 2;
        const int c   = ss & 3;
        ld_dst[j] = (isB ? 8192u : 0u) + (uint32_t)phys16(row, c) * 16u;
        ld_src[j] = (isB ? Bt + (size_t)(n0 + row) * K
                         : A  + (size_t)(m0 + row) * K) + c * 8;
    }

    const int hi = lane >> 4;
    const int rr = (lane & 7) + ((lane >> 3) & 1) * 8;
    uint32_t a_off[2][4], b_off[2][2];
    {
        const int ra = warpM + rr;
        const int la = ra >> 1, xa = (ra & 1) << 2, sa = la & 3;
        const int rb = warpN + rr;
        const int lb = rb >> 1, xb = (rb & 1) << 2, sb = lb & 3;
        #pragma unroll
        for (int ks = 0; ks < 2; ks++) {
            const int c = 2 * ks + hi;
            #pragma unroll
            for (int mt = 0; mt < 4; mt++)
                a_off[ks][mt] = (uint32_t)(la * 8 + mt * 64 + ((xa | c) ^ sa)) * 16u;
            #pragma unroll
            for (int n2 = 0; n2 < 2; n2++)
                b_off[ks][n2] = 8192u + (uint32_t)(lb * 8 + n2 * 64 + ((xb | c) ^ sb)) * 16u;
        }
    }

    float acc[4][4][4];
    #pragma unroll
    for (int mt = 0; mt < 4; mt++)
        #pragma unroll
        for (int nt = 0; nt < 4; nt++)
            #pragma unroll
            for (int c = 0; c < 4; c++) acc[mt][nt][c] = 0.f;

    const int nk = K >> 5;   // even, >= 32

    // prolog: stages 0..3 (one commit group each)
    for (int s = 0; s < 4; s++) {
        const uint32_t sb_ = smem_u + s * STAGE_B;
        #pragma unroll
        for (int j = 0; j < 4; j++)
            cp_async16(sb_ + ld_dst[j], ld_src[j] + s * 32);
        cp_commit();
    }

    int buf = 0;   // buffer index of chunk kc
    for (int kc = 0; kc < nk; kc += 2) {
        // stages kc, kc+1 must be complete. Newest pending groups are at most
        // {kc+2, kc+3}; at the tail fewer groups exist so wait0 on last iter.
        if (kc + 2 < nk) cp_wait2(); else cp_wait0();
        __syncthreads();

        // refill the two buffers retired last iteration (kc-2, kc-1)
        int i4 = buf + 4; if (i4 >= NSTAGE) i4 -= NSTAGE;
        int i5 = buf + 5; if (i5 >= NSTAGE) i5 -= NSTAGE;
        if (kc + 4 < nk) {
            const uint32_t sb_ = smem_u + i4 * STAGE_B;
            #pragma unroll
            for (int j = 0; j < 4; j++)
                cp_async16(sb_ + ld_dst[j], ld_src[j] + (kc + 4) * 32);
            cp_commit();
        }
        if (kc + 5 < nk) {
            const uint32_t sb_ = smem_u + i5 * STAGE_B;
            #pragma unroll
            for (int j = 0; j < 4; j++)
                cp_async16(sb_ + ld_dst[j], ld_src[j] + (kc + 5) * 32);
            cp_commit();
        }

        // compute chunks kc (buf) and kc+1 (buf+1)
        #pragma unroll
        for (int cc = 0; cc < 2; cc++) {
            int bi = buf + cc; if (bi >= NSTAGE) bi -= NSTAGE;
            const uint32_t st = smem_u + bi * STAGE_B;
            #pragma unroll
            for (int ks = 0; ks < 2; ks++) {
                uint32_t bfr[4][2];
                {
                    uint32_t r0, r1, r2, r3;
                    LDSM4(r0, r1, r2, r3, st + b_off[ks][0]);
                    bfr[0][0] = r0; bfr[1][0] = r1; bfr[0][1] = r2; bfr[1][1] = r3;
                }
                {
                    uint32_t r0, r1, r2, r3;
                    LDSM4(r0, r1, r2, r3, st + b_off[ks][1]);
                    bfr[2][0] = r0; bfr[3][0] = r1; bfr[2][1] = r2; bfr[3][1] = r3;
                }
                #pragma unroll
                for (int mt = 0; mt < 4; mt++) {
                    uint32_t af[4];
                    LDSM4(af[0], af[1], af[2], af[3], st + a_off[ks][mt]);
                    #pragma unroll
                    for (int nt = 0; nt < 4; nt++)
                        mma_f16(acc[mt][nt], af, bfr[nt]);
                }
            }
        }

        buf += 2; if (buf >= NSTAGE) buf -= NSTAGE;
    }

    if (outHalf) {
        __half* C = scratch_h(Cid);
        #pragma unroll
        for (int nt = 0; nt < 4; nt++) {
            const int n = n0 + warpN + nt * 8 + 2 * tig;
            const float b0 = bias[n], b1 = bias[n + 1];
            #pragma unroll
            for (int mt = 0; mt < 4; mt++) {
                const int m = m0 + warpM + mt * 16 + gid;
                float v0 = acc[mt][nt][0] + b0, v1 = acc[mt][nt][1] + b1;
                float v2 = acc[mt][nt][2] + b0, v3 = acc[mt][nt][3] + b1;
                if (relu) {
                    v0 = fmaxf(v0, 0.f); v1 = fmaxf(v1, 0.f);
                    v2 = fmaxf(v2, 0.f); v3 = fmaxf(v3, 0.f);
                }
                *(uint32_t*)&C[(size_t)m * N + n]       = packh2(v0, v1);
                *(uint32_t*)&C[(size_t)(m + 8) * N + n] = packh2(v2, v3);
            }
        }
    } else {
        float* C = scratch(Cid);
        #pragma unroll
        for (int nt = 0; nt < 4; nt++) {
            const int n = n0 + warpN + nt * 8 + 2 * tig;
            const float b0 = bias[n], b1 = bias[n + 1];
            #pragma unroll
            for (int mt = 0; mt < 4; mt++) {
                const int m = m0 + warpM + mt * 16 + gid;
                float2 v0 = make_float2(acc[mt][nt][0] + b0, acc[mt][nt][1] + b1);
                float2 v1 = make_float2(acc[mt][nt][2] + b0, acc[mt][nt][3] + b1);
                if (relu) {
                    v0.x = fmaxf(v0.x, 0.f); v0.y = fmaxf(v0.y, 0.f);
                    v1.x = fmaxf(v1.x, 0.f); v1.y = fmaxf(v1.y, 0.f);
                }
                *(float2*)&C[(size_t)m * N + n]       = v0;
                *(float2*)&C[(size_t)(m + 8) * N + n] = v1;
            }
        }
    }
}

// ---------------------------------------------------------------------------
// FP16 flash attention (R10-validated, unchanged)
// ---------------------------------------------------------------------------
__global__ __launch_bounds__(128)
void attn_f16()
{
    __shared__ __align__(16) uint8_t sm[16384];
    const uint32_t su = (uint32_t)__cvta_generic_to_shared(sm);

    const int nB  = blockIdx.z;
    const int h   = blockIdx.y;
    const int q0  = blockIdx.x * 128;
    const int tid = threadIdx.x;
    const int wid = tid >> 5;
    const int lane = tid & 31;
    const int gid  = lane >> 2;
    const int tig  = lane & 3;
    const int warpM = wid * 32;
    const int rr = (lane & 7) + ((lane >> 3) & 1) * 8;
    const int hi = lane >> 4;
    const float qscale = 0.125f * 1.44269504f;

    #pragma unroll
    for (int t = 0; t < 8; t++) {
        const int i = t * 128 + tid;
        const int row = i >> 3, c = i & 7;
        const __half* src = g_qkv16 + (size_t)(nB * LQ + q0 + row) * (3 * D) + h * HD + c * 8;
        *(uint4*)(sm + ATT_SEG(row, c) * 16) = *(const uint4*)src;
    }
    __syncthreads();

    uint32_t qf[2][4][4];
    #pragma unroll
    for (int mt = 0; mt < 2; mt++)
        #pragma unroll
        for (int kc = 0; kc < 4; kc++) {
            const int row = warpM + mt * 16 + rr;
            LDSM4(qf[mt][kc][0], qf[mt][kc][1], qf[mt][kc][2], qf[mt][kc][3],
                  su + ATT_SEG(row, 2 * kc + hi) * 16);
        }
    __syncthreads();

    float oac[2][8][4];
    #pragma unroll
    for (int mt = 0; mt < 2; mt++)
        #pragma unroll
        for (int nt = 0; nt < 8; nt++)
            #pragma unroll
            for (int c = 0; c < 4; c++) oac[mt][nt][c] = 0.f;
    float mrow[2][2] = {{-1e30f, -1e30f}, {-1e30f, -1e30f}};
    float lrow[2][2] = {{0.f, 0.f}, {0.f, 0.f}};

    for (int kt = 0; kt < LQ / 64; kt++) {
        #pragma unroll
        for (int t = 0; t < 4; t++) {
            const int i = t * 128 + tid;
            const int row = i >> 3, c = i & 7;
            const __half* base = g_qkv16 + (size_t)(nB * LQ + kt * 64 + row) * (3 * D) + h * HD + c * 8;
            *(uint4*)(sm + ATT_SEG(row, c) * 16)        = *(const uint4*)(base + D);
            *(uint4*)(sm + 8192 + ATT_SEG(row, c) * 16) = *(const uint4*)(base + 2 * D);
        }
        __syncthreads();

        float sacc[2][8][4];
        #pragma unroll
        for (int mt = 0; mt < 2; mt++)
            #pragma unroll
            for (int nt = 0; nt < 8; nt++)
                #pragma unroll
                for (int c = 0; c < 4; c++) sacc[mt][nt][c] = 0.f;

        #pragma unroll
        for (int ks = 0; ks < 4; ks++) {
            uint32_t bfr[8][2];
            #pragma unroll
            for (int np = 0; np < 4; np++) {
                uint32_t r0, r1, r2, r3;
                LDSM4(r0, r1, r2, r3, su + ATT_SEG(np * 16 + rr, 2 * ks + hi) * 16);
                bfr[2 * np][0] = r0; bfr[2 * np + 1][0] = r1;
                bfr[2 * np][1] = r2; bfr[2 * np + 1][1] = r3;
            }
            #pragma unroll
            for (int mt = 0; mt < 2; mt++)
                #pragma unroll
                for (int nt = 0; nt < 8; nt++)
                    mma_f16(sacc[mt][nt], qf[mt][ks], bfr[nt]);
        }

        #pragma unroll
        for (int mt = 0; mt < 2; mt++) {
            #pragma unroll
            for (int nt = 0; nt < 8; nt++) {
                sacc[mt][nt][0] *= qscale; sacc[mt][nt][1] *= qscale;
                sacc[mt][nt][2] *= qscale; sacc[mt][nt][3] *= qscale;
            }
            float mx0 = -1e30f, mx1 = -1e30f;
            #pragma unroll
            for (int nt = 0; nt < 8; nt++) {
                mx0 = fmaxf(mx0, fmaxf(sacc[mt][nt][0], sacc[mt][nt][1]));
                mx1 = fmaxf(mx1, fmaxf(sacc[mt][nt][2], sacc[mt][nt][3]));
            }
            mx0 = fmaxf(mx0, __shfl_xor_sync(0xFFFFFFFFu, mx0, 1));
            mx0 = fmaxf(mx0, __shfl_xor_sync(0xFFFFFFFFu, mx0, 2));
            mx1 = fmaxf(mx1, __shfl_xor_sync(0xFFFFFFFFu, mx1, 1));
            mx1 = fmaxf(mx1, __shfl_xor_sync(0xFFFFFFFFu, mx1, 2));

            const float mn0 = fmaxf(mrow[mt][0], mx0);
            const float mn1 = fmaxf(mrow[mt][1], mx1);
            const float cr0 = exp2f(mrow[mt][0] - mn0);
            const float cr1 = exp2f(mrow[mt][1] - mn1);
            mrow[mt][0] = mn0;
            mrow[mt][1] = mn1;

            float ls0 = 0.f, ls1 = 0.f;
            #pragma unroll
            for (int nt = 0; nt < 8; nt++) {
                sacc[mt][nt][0] = exp2f(sacc[mt][nt][0] - mn0);
                sacc[mt][nt][1] = exp2f(sacc[mt][nt][1] - mn0);
                sacc[mt][nt][2] = exp2f(sacc[mt][nt][2] - mn1);
                sacc[mt][nt][3] = exp2f(sacc[mt][nt][3] - mn1);
                ls0 += sacc[mt][nt][0] + sacc[mt][nt][1];
                ls1 += sacc[mt][nt][2] + sacc[mt][nt][3];
            }
            ls0 += __shfl_xor_sync(0xFFFFFFFFu, ls0, 1);
            ls0 += __shfl_xor_sync(0xFFFFFFFFu, ls0, 2);
            ls1 += __shfl_xor_sync(0xFFFFFFFFu, ls1, 1);
            ls1 += __shfl_xor_sync(0xFFFFFFFFu, ls1, 2);
            lrow[mt][0] = lrow[mt][0] * cr0 + ls0;
            lrow[mt][1] = lrow[mt][1] * cr1 + ls1;

            #pragma unroll
            for (int nt = 0; nt < 8; nt++) {
                oac[mt][nt][0] *= cr0; oac[mt][nt][1] *= cr0;
                oac[mt][nt][2] *= cr1; oac[mt][nt][3] *= cr1;
            }
        }

        #pragma unroll
        for (int kc = 0; kc < 4; kc++) {
            uint32_t vb[8][2];
            #pragma unroll
            for (int dp = 0; dp < 4; dp++) {
                uint32_t r0, r1, r2, r3;
                LDSM4T(r0, r1, r2, r3, su + 8192 + ATT_SEG(kc * 16 + rr, 2 * dp + hi) * 16);
                vb[2 * dp][0] = r0; vb[2 * dp][1] = r1;
                vb[2 * dp + 1][0] = r2; vb[2 * dp + 1][1] = r3;
            }
            uint32_t pa[2][4];
            #pragma unroll
            for (int mt = 0; mt < 2; mt++) {
                pa[mt][0] = packh2(sacc[mt][2 * kc][0],     sacc[mt][2 * kc][1]);
                pa[mt][1] = packh2(sacc[mt][2 * kc][2],     sacc[mt][2 * kc][3]);
                pa[mt][2] = packh2(sacc[mt][2 * kc + 1][0], sacc[mt][2 * kc + 1][1]);
                pa[mt][3] = packh2(sacc[mt][2 * kc + 1][2], sacc[mt][2 * kc + 1][3]);
            }
            #pragma unroll
            for (int mt = 0; mt < 2; mt++)
                #pragma unroll
                for (int ntd = 0; ntd < 8; ntd++)
                    mma_f16(oac[mt][ntd], pa[mt], vb[ntd]);
        }
        __syncthreads();
    }

    #pragma unroll
    for (int mt = 0; mt < 2; mt++) {
        const float inv0 = 1.f / lrow[mt][0];
        const float inv1 = 1.f / lrow[mt][1];
        const int grow = nB * LQ + q0 + warpM + mt * 16 + gid;
        #pragma unroll
        for (int ntd = 0; ntd < 8; ntd++) {
            const int col = h * HD + ntd * 8 + 2 * tig;
            *(uint32_t*)&g_attn16[(size_t)grow * D + col] =
                packh2(oac[mt][ntd][0] * inv0, oac[mt][ntd][1] * inv0);
            *(uint32_t*)&g_attn16[(size_t)(grow + 8) * D + col] =
                packh2(oac[mt][ntd][2] * inv1, oac[mt][ntd][3] * inv1);
        }
    }
}

// ---------------------------------------------------------------------------
// Residual add + LayerNorm (optional fp16 shadow)
// ---------------------------------------------------------------------------
__global__ __launch_bounds__(256)
void add_ln_kernel(const float* __restrict__ aext, int aid,
                   const float* __restrict__ bext, int bid,
                   const float* __restrict__ gamma,
                   const float* __restrict__ beta,
                   float* __restrict__ outext, int outid, int hOutId)
{
    const float* a = aext ? aext : scratch(aid);
    const float* b = bext ? bext : scratch(bid);
    float*       o = outext ? outext : scratch(outid);

    const int row = blockIdx.x;
    const int tid = threadIdx.x;
    const size_t base = (size_t)row * D;

    float v[4];
    float s = 0.f, s2 = 0.f;
    #pragma unroll
    for (int i = 0; i < 4; i++) {
        int col = tid + i * 256;
        float x = a[base + col] + b[base + col];
        v[i] = x;
        s  += x;
        s2 += x * x;
    }
    #pragma unroll
    for (int off = 16; off; off >>= 1) {
        s  += __shfl_xor_sync(0xFFFFFFFFu, s,  off);
        s2 += __shfl_xor_sync(0xFFFFFFFFu, s2, off);
    }
    __shared__ float rs[8], rs2[8];
    const int warp = tid >> 5, lane = tid & 31;
    if (lane == 0) { rs[warp] = s; rs2[warp] = s2; }
    __syncthreads();
    float ts = 0.f, ts2 = 0.f;
    #pragma unroll
    for (int w = 0; w < 8; w++) { ts += rs[w]; ts2 += rs2[w]; }

    const float mu  = ts * (1.f / D);
    const float var = ts2 * (1.f / D) - mu * mu;
    const float inv = rsqrtf(var + EPS);

    __half* ho = (hOutId >= 0) ? scratch_h(hOutId) : (__half*)0;
    #pragma unroll
    for (int i = 0; i < 4; i++) {
        int col = tid + i * 256;
        float r = (v[i] - mu) * inv * gamma[col] + beta[col];
        o[base + col] = r;
        if (ho) ho[base + col] = __float2half(r);
    }
}

// ---------------------------------------------------------------------------
// Launch
// ---------------------------------------------------------------------------
extern "C" void kernel_launch(void* const* d_in, const int* in_sizes, int n_in,
                              void* d_out, int out_size)
{
    const float* x     = (const float*)d_in[0];
    const float* w_qkv = (const float*)d_in[1];
    const float* b_qkv = (const float*)d_in[2];
    const float* w_o   = (const float*)d_in[3];
    const float* b_o   = (const float*)d_in[4];
    const float* g1    = (const float*)d_in[5];
    const float* be1   = (const float*)d_in[6];
    const float* w1    = (const float*)d_in[7];
    const float* b1    = (const float*)d_in[8];
    const float* w2    = (const float*)d_in[9];
    const float* b2    = (const float*)d_in[10];
    const float* g2    = (const float*)d_in[11];
    const float* be2   = (const float*)d_in[12];
    float* out = (float*)d_out;

    cudaFuncSetAttribute(gemm_f16,
                         cudaFuncAttributeMaxDynamicSharedMemorySize, GEMM_SMEM);

    // operand prep
    cvt16_k<<<MROWS * D / 1024, 256>>>(x, 0);
    transpose_k<<<dim3(3 * D / 32, D / 32), 256>>>(w_qkv, 4, D, 3 * D);
    transpose_k<<<dim3(D / 32,     D / 32), 256>>>(w_o,   5, D, D);
    transpose_k<<<dim3(FF / 32,    D / 32), 256>>>(w1,    6, D, FF);
    transpose_k<<<dim3(D / 32,    FF / 32), 256>>>(w2,    7, FF, D);

    // 1. QKV: x16 @ wqkvT16 -> g_qkv16 (fp16)
    gemm_f16<<<dim3(3 * D / 128, MROWS / 128), 256, GEMM_SMEM>>>(
        0, 4, b_qkv, 8, 1, MROWS, 3 * D, D, 0);

    // 2. attention (fp16 tensor-core flash) -> g_attn16
    attn_f16<<<dim3(LQ / 128, H_, NB), 128>>>();

    // 3. proj: attn16 @ woT16 -> g_proj (fp32)
    gemm_f16<<<dim3(D / 128, MROWS / 128), 256, GEMM_SMEM>>>(
        1, 5, b_o, 0, 0, MROWS, D, D, 0);

    // 4. h = LN(proj + x) -> g_h (fp32) + g_h16
    add_ln_kernel<<<MROWS, 256>>>(nullptr, 0, x, -1, g1, be1, nullptr, 1, 2);

    // 5. FF1: h16 @ w1T16 + ReLU -> g_ff116 (fp16)
    gemm_f16<<<dim3(FF / 128, MROWS / 128), 256, GEMM_SMEM>>>(
        2, 6, b1, 3, 1, MROWS, FF, D, 1);

    // 6. FF2: ff116 @ w2T16 -> g_ff2 (fp32)
    gemm_f16<<<dim3(D / 128, MROWS / 128), 256, GEMM_SMEM>>>(
        3, 7, b2, 2, 0, MROWS, D, FF, 0);

    // 7. out = LN(h + ff2)
    add_ln_kernel<<<MROWS, 256>>>(nullptr, 1, nullptr, 2, g2, be2, out, -1, -1);
}

// round 14
// speedup vs baseline: 1.0897x; 1.0897x over previous
#include <cuda_runtime.h>
#include <cuda_fp16.h>
#include <math.h>
#include <stdint.h>

// Problem constants
#define D     1024
#define H_    16
#define HD    64
#define FF    4096
#define NB    2
#define LQ    2048
#define MROWS (NB * LQ)   // 4096
#define EPS   1e-5f

// ---------------------------------------------------------------------------
// Scratch (device globals — no allocation allowed)
// ---------------------------------------------------------------------------
__device__ float g_proj[MROWS * D];       // fp32 id 0
__device__ float g_h   [MROWS * D];       // fp32 id 1
__device__ float g_ff2 [MROWS * D];       // fp32 id 2

__device__ __half g_x16   [MROWS * D];    // h id 0
__device__ __half g_attn16[MROWS * D];    // h id 1
__device__ __half g_h16   [MROWS * D];    // h id 2
__device__ __half g_ff116 [MROWS * FF];   // h id 3
__device__ __half g_wqkvT16[3 * D * D];   // h id 4
__device__ __half g_woT16 [D * D];        // h id 5
__device__ __half g_w1T16 [FF * D];       // h id 6
__device__ __half g_w2T16 [D * FF];       // h id 7
__device__ __half g_qkv16 [MROWS * 3 * D];// h id 8

__device__ __forceinline__ float* scratch(int id) {
    switch (id) {
        case 0:  return g_proj;
        case 1:  return g_h;
        default: return g_ff2;
    }
}
__device__ __forceinline__ __half* scratch_h(int id) {
    switch (id) {
        case 0:  return g_x16;
        case 1:  return g_attn16;
        case 2:  return g_h16;
        case 3:  return g_ff116;
        case 4:  return g_wqkvT16;
        case 5:  return g_woT16;
        case 6:  return g_w1T16;
        case 7:  return g_w2T16;
        default: return g_qkv16;
    }
}

// ---------------------------------------------------------------------------
// mma / async helpers (base sm_103 target OK)
// ---------------------------------------------------------------------------
__device__ __forceinline__ void mma_f16(float* c, const uint32_t* a, const uint32_t* b) {
    asm volatile(
        "mma.sync.aligned.m16n8k16.row.col.f32.f16.f16.f32 "
        "{%0,%1,%2,%3}, {%4,%5,%6,%7}, {%8,%9}, {%0,%1,%2,%3};"
        : "+f"(c[0]), "+f"(c[1]), "+f"(c[2]), "+f"(c[3])
        : "r"(a[0]), "r"(a[1]), "r"(a[2]), "r"(a[3]),
          "r"(b[0]), "r"(b[1]));
}

__device__ __forceinline__ uint32_t packh2(float a, float b) {
    __half2 h = __floats2half2_rn(a, b);
    return *(uint32_t*)&h;
}

__device__ __forceinline__ void cp_async16(uint32_t dst, const void* src) {
    asm volatile("cp.async.cg.shared.global [%0], [%1], 16;" :: "r"(dst), "l"(src));
}
__device__ __forceinline__ void cp_commit() {
    asm volatile("cp.async.commit_group;" ::: "memory");
}
__device__ __forceinline__ void cp_wait2() {
    asm volatile("cp.async.wait_group 2;" ::: "memory");
}

#define LDSM4(r0, r1, r2, r3, addr) \
    asm volatile("ldmatrix.sync.aligned.m8n8.x4.shared.b16 {%0,%1,%2,%3}, [%4];" \
                 : "=r"(r0), "=r"(r1), "=r"(r2), "=r"(r3) : "r"(addr))

#define LDSM4T(r0, r1, r2, r3, addr) \
    asm volatile("ldmatrix.sync.aligned.m8n8.x4.trans.shared.b16 {%0,%1,%2,%3}, [%4];" \
                 : "=r"(r0), "=r"(r1), "=r"(r2), "=r"(r3) : "r"(addr))

// 64B-row XOR swizzle (GEMM stages): 16B segment for (row, chunk c in 0..3)
__device__ __forceinline__ int phys16(int row, int c) {
    return (row >> 1) * 8 + ((((row & 1) << 2) | c) ^ ((row >> 1) & 3));
}
// 128B-row XOR swizzle (attention tiles): seg for (row, seg-col c in 0..7)
#define ATT_SEG(row, c) (((row) * 8) + ((c) ^ ((row) & 7)))

// ---------------------------------------------------------------------------
// Fused operand prep: x->fp16 + 4 weight transposes in ONE kernel.
// Flat block dispatch; all branches use 256 threads.
//   [0, 4096)          : cvt x -> g_x16
//   [4096, 7168)       : w_qkv^T -> id4   (R=1024 rows src, C=3072)  96x32 tiles
//   [7168, 8192)       : w_o^T   -> id5   (C=1024)                   32x32
//   [8192, 12288)      : w1^T    -> id6   (C=4096)                  128x32
//   [12288, 16384)     : w2^T    -> id7   (R=4096, C=1024)           32x128
// ---------------------------------------------------------------------------
__device__ __forceinline__ void transpose_tile(const float* __restrict__ src,
                                               __half* __restrict__ dst,
                                               int R, int C, int bx, int by,
                                               float (*t)[33])
{
    const int tx = threadIdx.x & 31;
    const int ty = threadIdx.x >> 5;
    #pragma unroll
    for (int i = 0; i < 32; i += 8)
        t[ty + i][tx] = src[(size_t)(by + ty + i) * C + bx + tx];
    __syncthreads();
    #pragma unroll
    for (int i = 0; i < 32; i += 8)
        dst[(size_t)(bx + ty + i) * R + by + tx] = __float2half(t[tx][ty + i]);
}

__global__ __launch_bounds__(256)
void prep_k(const float* __restrict__ x,
            const float* __restrict__ w_qkv,
            const float* __restrict__ w_o,
            const float* __restrict__ w1,
            const float* __restrict__ w2)
{
    __shared__ float t[32][33];
    const int id = blockIdx.x;

    if (id < 4096) {
        // cvt: 1024 floats per block
        uint32_t* d = (uint32_t*)g_x16;
        const int i = id * 256 + threadIdx.x;
        const float4 v = ((const float4*)x)[i];
        d[i * 2 + 0] = packh2(v.x, v.y);
        d[i * 2 + 1] = packh2(v.z, v.w);
    } else if (id < 7168) {
        const int b = id - 4096;                    // 96 x 32
        transpose_tile(w_qkv, g_wqkvT16, D, 3 * D, (b % 96) * 32, (b / 96) * 32, t);
    } else if (id < 8192) {
        const int b = id - 7168;                    // 32 x 32
        transpose_tile(w_o, g_woT16, D, D, (b % 32) * 32, (b / 32) * 32, t);
    } else if (id < 12288) {
        const int b = id - 8192;                    // 128 x 32
        transpose_tile(w1, g_w1T16, D, FF, (b % 128) * 32, (b / 128) * 32, t);
    } else {
        const int b = id - 12288;                   // 32 x 128
        transpose_tile(w2, g_w2T16, FF, D, (b % 32) * 32, (b / 32) * 32, t);
    }
}

// ---------------------------------------------------------------------------
// FP16 GEMM 128x128 (R10-validated): 8 warps 64x32, BK=32, 4-stage cp.async
// ---------------------------------------------------------------------------
#define STAGE_B 16384
#define GEMM_SMEM (4 * STAGE_B)   // 65536

__global__ __launch_bounds__(256)
void gemm_f16(int Aid, int Bid, const float* __restrict__ bias,
              int Cid, int outHalf, int M, int N, int K, int relu)
{
    extern __shared__ char smem[];
    const uint32_t smem_u = (uint32_t)__cvta_generic_to_shared(smem);

    const __half* A  = scratch_h(Aid);
    const __half* Bt = scratch_h(Bid);

    const int tid  = threadIdx.x;
    const int wid  = tid >> 5;
    const int lane = tid & 31;
    const int gid  = lane >> 2;
    const int tig  = lane & 3;
    const int warpM = (wid & 1) * 64;
    const int warpN = (wid >> 1) * 32;
    const int m0 = blockIdx.y * 128;
    const int n0 = blockIdx.x * 128;

    uint32_t ld_dst[4];
    const __half* ld_src[4];
    #pragma unroll
    for (int j = 0; j < 4; j++) {
        const int s   = j * 256 + tid;
        const int isB = s >= 512;
        const int ss  = s & 511;
        const int row = ss >> 2;
        const int c   = ss & 3;
        ld_dst[j] = (isB ? 8192u : 0u) + (uint32_t)phys16(row, c) * 16u;
        ld_src[j] = (isB ? Bt + (size_t)(n0 + row) * K
                         : A  + (size_t)(m0 + row) * K) + c * 8;
    }

    const int hi = lane >> 4;
    const int rr = (lane & 7) + ((lane >> 3) & 1) * 8;
    uint32_t a_off[2][4], b_off[2][2];
    {
        const int ra = warpM + rr;
        const int la = ra >> 1, xa = (ra & 1) << 2, sa = la & 3;
        const int rb = warpN + rr;
        const int lb = rb >> 1, xb = (rb & 1) << 2, sb = lb & 3;
        #pragma unroll
        for (int ks = 0; ks < 2; ks++) {
            const int c = 2 * ks + hi;
            #pragma unroll
            for (int mt = 0; mt < 4; mt++)
                a_off[ks][mt] = (uint32_t)(la * 8 + mt * 64 + ((xa | c) ^ sa)) * 16u;
            #pragma unroll
            for (int n2 = 0; n2 < 2; n2++)
                b_off[ks][n2] = 8192u + (uint32_t)(lb * 8 + n2 * 64 + ((xb | c) ^ sb)) * 16u;
        }
    }

    float acc[4][4][4];
    #pragma unroll
    for (int mt = 0; mt < 4; mt++)
        #pragma unroll
        for (int nt = 0; nt < 4; nt++)
            #pragma unroll
            for (int c = 0; c < 4; c++) acc[mt][nt][c] = 0.f;

    const int nk = K >> 5;

    for (int s = 0; s < 3; s++) {
        const uint32_t sb_ = smem_u + s * STAGE_B;
        #pragma unroll
        for (int j = 0; j < 4; j++)
            cp_async16(sb_ + ld_dst[j], ld_src[j] + s * 32);
        cp_commit();
    }

    for (int kc = 0; kc < nk; kc++) {
        cp_wait2();
        __syncthreads();

        if (kc + 3 < nk) {
            const uint32_t sb_ = smem_u + ((kc + 3) & 3) * STAGE_B;
            #pragma unroll
            for (int j = 0; j < 4; j++)
                cp_async16(sb_ + ld_dst[j], ld_src[j] + (kc + 3) * 32);
        }
        cp_commit();

        const uint32_t st = smem_u + (kc & 3) * STAGE_B;
        #pragma unroll
        for (int ks = 0; ks < 2; ks++) {
            uint32_t bfr[4][2];
            {
                uint32_t r0, r1, r2, r3;
                LDSM4(r0, r1, r2, r3, st + b_off[ks][0]);
                bfr[0][0] = r0; bfr[1][0] = r1; bfr[0][1] = r2; bfr[1][1] = r3;
            }
            {
                uint32_t r0, r1, r2, r3;
                LDSM4(r0, r1, r2, r3, st + b_off[ks][1]);
                bfr[2][0] = r0; bfr[3][0] = r1; bfr[2][1] = r2; bfr[3][1] = r3;
            }
            #pragma unroll
            for (int mt = 0; mt < 4; mt++) {
                uint32_t af[4];
                LDSM4(af[0], af[1], af[2], af[3], st + a_off[ks][mt]);
                #pragma unroll
                for (int nt = 0; nt < 4; nt++)
                    mma_f16(acc[mt][nt], af, bfr[nt]);
            }
        }
    }

    if (outHalf) {
        __half* C = scratch_h(Cid);
        #pragma unroll
        for (int nt = 0; nt < 4; nt++) {
            const int n = n0 + warpN + nt * 8 + 2 * tig;
            const float b0 = bias[n], b1 = bias[n + 1];
            #pragma unroll
            for (int mt = 0; mt < 4; mt++) {
                const int m = m0 + warpM + mt * 16 + gid;
                float v0 = acc[mt][nt][0] + b0, v1 = acc[mt][nt][1] + b1;
                float v2 = acc[mt][nt][2] + b0, v3 = acc[mt][nt][3] + b1;
                if (relu) {
                    v0 = fmaxf(v0, 0.f); v1 = fmaxf(v1, 0.f);
                    v2 = fmaxf(v2, 0.f); v3 = fmaxf(v3, 0.f);
                }
                *(uint32_t*)&C[(size_t)m * N + n]       = packh2(v0, v1);
                *(uint32_t*)&C[(size_t)(m + 8) * N + n] = packh2(v2, v3);
            }
        }
    } else {
        float* C = scratch(Cid);
        #pragma unroll
        for (int nt = 0; nt < 4; nt++) {
            const int n = n0 + warpN + nt * 8 + 2 * tig;
            const float b0 = bias[n], b1 = bias[n + 1];
            #pragma unroll
            for (int mt = 0; mt < 4; mt++) {
                const int m = m0 + warpM + mt * 16 + gid;
                float2 v0 = make_float2(acc[mt][nt][0] + b0, acc[mt][nt][1] + b1);
                float2 v1 = make_float2(acc[mt][nt][2] + b0, acc[mt][nt][3] + b1);
                if (relu) {
                    v0.x = fmaxf(v0.x, 0.f); v0.y = fmaxf(v0.y, 0.f);
                    v1.x = fmaxf(v1.x, 0.f); v1.y = fmaxf(v1.y, 0.f);
                }
                *(float2*)&C[(size_t)m * N + n]       = v0;
                *(float2*)&C[(size_t)(m + 8) * N + n] = v1;
            }
        }
    }
}

// ---------------------------------------------------------------------------
// FP16 flash attention (R10-validated, unchanged)
// ---------------------------------------------------------------------------
__global__ __launch_bounds__(128)
void attn_f16()
{
    __shared__ __align__(16) uint8_t sm[16384];
    const uint32_t su = (uint32_t)__cvta_generic_to_shared(sm);

    const int nB  = blockIdx.z;
    const int h   = blockIdx.y;
    const int q0  = blockIdx.x * 128;
    const int tid = threadIdx.x;
    const int wid = tid >> 5;
    const int lane = tid & 31;
    const int gid  = lane >> 2;
    const int tig  = lane & 3;
    const int warpM = wid * 32;
    const int rr = (lane & 7) + ((lane >> 3) & 1) * 8;
    const int hi = lane >> 4;
    const float qscale = 0.125f * 1.44269504f;

    #pragma unroll
    for (int t = 0; t < 8; t++) {
        const int i = t * 128 + tid;
        const int row = i >> 3, c = i & 7;
        const __half* src = g_qkv16 + (size_t)(nB * LQ + q0 + row) * (3 * D) + h * HD + c * 8;
        *(uint4*)(sm + ATT_SEG(row, c) * 16) = *(const uint4*)src;
    }
    __syncthreads();

    uint32_t qf[2][4][4];
    #pragma unroll
    for (int mt = 0; mt < 2; mt++)
        #pragma unroll
        for (int kc = 0; kc < 4; kc++) {
            const int row = warpM + mt * 16 + rr;
            LDSM4(qf[mt][kc][0], qf[mt][kc][1], qf[mt][kc][2], qf[mt][kc][3],
                  su + ATT_SEG(row, 2 * kc + hi) * 16);
        }
    __syncthreads();

    float oac[2][8][4];
    #pragma unroll
    for (int mt = 0; mt < 2; mt++)
        #pragma unroll
        for (int nt = 0; nt < 8; nt++)
            #pragma unroll
            for (int c = 0; c < 4; c++) oac[mt][nt][c] = 0.f;
    float mrow[2][2] = {{-1e30f, -1e30f}, {-1e30f, -1e30f}};
    float lrow[2][2] = {{0.f, 0.f}, {0.f, 0.f}};

    for (int kt = 0; kt < LQ / 64; kt++) {
        #pragma unroll
        for (int t = 0; t < 4; t++) {
            const int i = t * 128 + tid;
            const int row = i >> 3, c = i & 7;
            const __half* base = g_qkv16 + (size_t)(nB * LQ + kt * 64 + row) * (3 * D) + h * HD + c * 8;
            *(uint4*)(sm + ATT_SEG(row, c) * 16)        = *(const uint4*)(base + D);
            *(uint4*)(sm + 8192 + ATT_SEG(row, c) * 16) = *(const uint4*)(base + 2 * D);
        }
        __syncthreads();

        float sacc[2][8][4];
        #pragma unroll
        for (int mt = 0; mt < 2; mt++)
            #pragma unroll
            for (int nt = 0; nt < 8; nt++)
                #pragma unroll
                for (int c = 0; c < 4; c++) sacc[mt][nt][c] = 0.f;

        #pragma unroll
        for (int ks = 0; ks < 4; ks++) {
            uint32_t bfr[8][2];
            #pragma unroll
            for (int np = 0; np < 4; np++) {
                uint32_t r0, r1, r2, r3;
                LDSM4(r0, r1, r2, r3, su + ATT_SEG(np * 16 + rr, 2 * ks + hi) * 16);
                bfr[2 * np][0] = r0; bfr[2 * np + 1][0] = r1;
                bfr[2 * np][1] = r2; bfr[2 * np + 1][1] = r3;
            }
            #pragma unroll
            for (int mt = 0; mt < 2; mt++)
                #pragma unroll
                for (int nt = 0; nt < 8; nt++)
                    mma_f16(sacc[mt][nt], qf[mt][ks], bfr[nt]);
        }

        #pragma unroll
        for (int mt = 0; mt < 2; mt++) {
            #pragma unroll
            for (int nt = 0; nt < 8; nt++) {
                sacc[mt][nt][0] *= qscale; sacc[mt][nt][1] *= qscale;
                sacc[mt][nt][2] *= qscale; sacc[mt][nt][3] *= qscale;
            }
            float mx0 = -1e30f, mx1 = -1e30f;
            #pragma unroll
            for (int nt = 0; nt < 8; nt++) {
                mx0 = fmaxf(mx0, fmaxf(sacc[mt][nt][0], sacc[mt][nt][1]));
                mx1 = fmaxf(mx1, fmaxf(sacc[mt][nt][2], sacc[mt][nt][3]));
            }
            mx0 = fmaxf(mx0, __shfl_xor_sync(0xFFFFFFFFu, mx0, 1));
            mx0 = fmaxf(mx0, __shfl_xor_sync(0xFFFFFFFFu, mx0, 2));
            mx1 = fmaxf(mx1, __shfl_xor_sync(0xFFFFFFFFu, mx1, 1));
            mx1 = fmaxf(mx1, __shfl_xor_sync(0xFFFFFFFFu, mx1, 2));

            const float mn0 = fmaxf(mrow[mt][0], mx0);
            const float mn1 = fmaxf(mrow[mt][1], mx1);
            const float cr0 = exp2f(mrow[mt][0] - mn0);
            const float cr1 = exp2f(mrow[mt][1] - mn1);
            mrow[mt][0] = mn0;
            mrow[mt][1] = mn1;

            float ls0 = 0.f, ls1 = 0.f;
            #pragma unroll
            for (int nt = 0; nt < 8; nt++) {
                sacc[mt][nt][0] = exp2f(sacc[mt][nt][0] - mn0);
                sacc[mt][nt][1] = exp2f(sacc[mt][nt][1] - mn0);
                sacc[mt][nt][2] = exp2f(sacc[mt][nt][2] - mn1);
                sacc[mt][nt][3] = exp2f(sacc[mt][nt][3] - mn1);
                ls0 += sacc[mt][nt][0] + sacc[mt][nt][1];
                ls1 += sacc[mt][nt][2] + sacc[mt][nt][3];
            }
            ls0 += __shfl_xor_sync(0xFFFFFFFFu, ls0, 1);
            ls0 += __shfl_xor_sync(0xFFFFFFFFu, ls0, 2);
            ls1 += __shfl_xor_sync(0xFFFFFFFFu, ls1, 1);
            ls1 += __shfl_xor_sync(0xFFFFFFFFu, ls1, 2);
            lrow[mt][0] = lrow[mt][0] * cr0 + ls0;
            lrow[mt][1] = lrow[mt][1] * cr1 + ls1;

            #pragma unroll
            for (int nt = 0; nt < 8; nt++) {
                oac[mt][nt][0] *= cr0; oac[mt][nt][1] *= cr0;
                oac[mt][nt][2] *= cr1; oac[mt][nt][3] *= cr1;
            }
        }

        #pragma unroll
        for (int kc = 0; kc < 4; kc++) {
            uint32_t vb[8][2];
            #pragma unroll
            for (int dp = 0; dp < 4; dp++) {
                uint32_t r0, r1, r2, r3;
                LDSM4T(r0, r1, r2, r3, su + 8192 + ATT_SEG(kc * 16 + rr, 2 * dp + hi) * 16);
                vb[2 * dp][0] = r0; vb[2 * dp][1] = r1;
                vb[2 * dp + 1][0] = r2; vb[2 * dp + 1][1] = r3;
            }
            uint32_t pa[2][4];
            #pragma unroll
            for (int mt = 0; mt < 2; mt++) {
                pa[mt][0] = packh2(sacc[mt][2 * kc][0],     sacc[mt][2 * kc][1]);
                pa[mt][1] = packh2(sacc[mt][2 * kc][2],     sacc[mt][2 * kc][3]);
                pa[mt][2] = packh2(sacc[mt][2 * kc + 1][0], sacc[mt][2 * kc + 1][1]);
                pa[mt][3] = packh2(sacc[mt][2 * kc + 1][2], sacc[mt][2 * kc + 1][3]);
            }
            #pragma unroll
            for (int mt = 0; mt < 2; mt++)
                #pragma unroll
                for (int ntd = 0; ntd < 8; ntd++)
                    mma_f16(oac[mt][ntd], pa[mt], vb[ntd]);
        }
        __syncthreads();
    }

    #pragma unroll
    for (int mt = 0; mt < 2; mt++) {
        const float inv0 = 1.f / lrow[mt][0];
        const float inv1 = 1.f / lrow[mt][1];
        const int grow = nB * LQ + q0 + warpM + mt * 16 + gid;
        #pragma unroll
        for (int ntd = 0; ntd < 8; ntd++) {
            const int col = h * HD + ntd * 8 + 2 * tig;
            *(uint32_t*)&g_attn16[(size_t)grow * D + col] =
                packh2(oac[mt][ntd][0] * inv0, oac[mt][ntd][1] * inv0);
            *(uint32_t*)&g_attn16[(size_t)(grow + 8) * D + col] =
                packh2(oac[mt][ntd][2] * inv1, oac[mt][ntd][3] * inv1);
        }
    }
}

// ---------------------------------------------------------------------------
// Residual add + LayerNorm (optional fp16 shadow)
// ---------------------------------------------------------------------------
__global__ __launch_bounds__(256)
void add_ln_kernel(const float* __restrict__ aext, int aid,
                   const float* __restrict__ bext, int bid,
                   const float* __restrict__ gamma,
                   const float* __restrict__ beta,
                   float* __restrict__ outext, int outid, int hOutId)
{
    const float* a = aext ? aext : scratch(aid);
    const float* b = bext ? bext : scratch(bid);
    float*       o = outext ? outext : scratch(outid);

    const int row = blockIdx.x;
    const int tid = threadIdx.x;
    const size_t base = (size_t)row * D;

    float v[4];
    float s = 0.f, s2 = 0.f;
    #pragma unroll
    for (int i = 0; i < 4; i++) {
        int col = tid + i * 256;
        float x = a[base + col] + b[base + col];
        v[i] = x;
        s  += x;
        s2 += x * x;
    }
    #pragma unroll
    for (int off = 16; off; off >>= 1) {
        s  += __shfl_xor_sync(0xFFFFFFFFu, s,  off);
        s2 += __shfl_xor_sync(0xFFFFFFFFu, s2, off);
    }
    __shared__ float rs[8], rs2[8];
    const int warp = tid >> 5, lane = tid & 31;
    if (lane == 0) { rs[warp] = s; rs2[warp] = s2; }
    __syncthreads();
    float ts = 0.f, ts2 = 0.f;
    #pragma unroll
    for (int w = 0; w < 8; w++) { ts += rs[w]; ts2 += rs2[w]; }

    const float mu  = ts * (1.f / D);
    const float var = ts2 * (1.f / D) - mu * mu;
    const float inv = rsqrtf(var + EPS);

    __half* ho = (hOutId >= 0) ? scratch_h(hOutId) : (__half*)0;
    #pragma unroll
    for (int i = 0; i < 4; i++) {
        int col = tid + i * 256;
        float r = (v[i] - mu) * inv * gamma[col] + beta[col];
        o[base + col] = r;
        if (ho) ho[base + col] = __float2half(r);
    }
}

// ---------------------------------------------------------------------------
// Launch
// ---------------------------------------------------------------------------
extern "C" void kernel_launch(void* const* d_in, const int* in_sizes, int n_in,
                              void* d_out, int out_size)
{
    const float* x     = (const float*)d_in[0];
    const float* w_qkv = (const float*)d_in[1];
    const float* b_qkv = (const float*)d_in[2];
    const float* w_o   = (const float*)d_in[3];
    const float* b_o   = (const float*)d_in[4];
    const float* g1    = (const float*)d_in[5];
    const float* be1   = (const float*)d_in[6];
    const float* w1    = (const float*)d_in[7];
    const float* b1    = (const float*)d_in[8];
    const float* w2    = (const float*)d_in[9];
    const float* b2    = (const float*)d_in[10];
    const float* g2    = (const float*)d_in[11];
    const float* be2   = (const float*)d_in[12];
    float* out = (float*)d_out;

    cudaFuncSetAttribute(gemm_f16,
                         cudaFuncAttributeMaxDynamicSharedMemorySize, GEMM_SMEM);

    // 0. fused operand prep (cvt x + 4 transposes) — one wave
    prep_k<<<16384, 256>>>(x, w_qkv, w_o, w1, w2);

    // 1. QKV: x16 @ wqkvT16 -> g_qkv16 (fp16)
    gemm_f16<<<dim3(3 * D / 128, MROWS / 128), 256, GEMM_SMEM>>>(
        0, 4, b_qkv, 8, 1, MROWS, 3 * D, D, 0);

    // 2. attention (fp16 tensor-core flash) -> g_attn16
    attn_f16<<<dim3(LQ / 128, H_, NB), 128>>>();

    // 3. proj: attn16 @ woT16 -> g_proj (fp32)
    gemm_f16<<<dim3(D / 128, MROWS / 128), 256, GEMM_SMEM>>>(
        1, 5, b_o, 0, 0, MROWS, D, D, 0);

    // 4. h = LN(proj + x) -> g_h (fp32) + g_h16
    add_ln_kernel<<<MROWS, 256>>>(nullptr, 0, x, -1, g1, be1, nullptr, 1, 2);

    // 5. FF1: h16 @ w1T16 + ReLU -> g_ff116 (fp16)
    gemm_f16<<<dim3(FF / 128, MROWS / 128), 256, GEMM_SMEM>>>(
        2, 6, b1, 3, 1, MROWS, FF, D, 1);

    // 6. FF2: ff116 @ w2T16 -> g_ff2 (fp32)
    gemm_f16<<<dim3(D / 128, MROWS / 128), 256, GEMM_SMEM>>>(
        3, 7, b2, 2, 0, MROWS, D, FF, 0);

    // 7. out = LN(h + ff2)
    add_ln_kernel<<<MROWS, 256>>>(nullptr, 1, nullptr, 2, g2, be2, out, -1, -1);
}

// round 15
// speedup vs baseline: 1.1038x; 1.0129x over previous
#include <cuda_runtime.h>
#include <cuda_fp16.h>
#include <math.h>
#include <stdint.h>

// Problem constants
#define D     1024
#define H_    16
#define HD    64
#define FF    4096
#define NB    2
#define LQ    2048
#define MROWS (NB * LQ)   // 4096
#define EPS   1e-5f

// ---------------------------------------------------------------------------
// Scratch (device globals — no allocation allowed)
// ---------------------------------------------------------------------------
__device__ float g_f32 [MROWS * D];       // fp32 spare (unused data path)

__device__ __half g_x16   [MROWS * D];    // h id 0  (x16, later proj16)
__device__ __half g_attn16[MROWS * D];    // h id 1  (attn16, later ff216)
__device__ __half g_h16   [MROWS * D];    // h id 2
__device__ __half g_ff116 [MROWS * FF];   // h id 3
__device__ __half g_wqkvT16[3 * D * D];   // h id 4
__device__ __half g_woT16 [D * D];        // h id 5
__device__ __half g_w1T16 [FF * D];       // h id 6
__device__ __half g_w2T16 [D * FF];       // h id 7
__device__ __half g_qkv16 [MROWS * 3 * D];// h id 8

__device__ __forceinline__ float* scratch(int id) {
    (void)id;
    return g_f32;
}
__device__ __forceinline__ __half* scratch_h(int id) {
    switch (id) {
        case 0:  return g_x16;
        case 1:  return g_attn16;
        case 2:  return g_h16;
        case 3:  return g_ff116;
        case 4:  return g_wqkvT16;
        case 5:  return g_woT16;
        case 6:  return g_w1T16;
        case 7:  return g_w2T16;
        default: return g_qkv16;
    }
}

// ---------------------------------------------------------------------------
// mma / async helpers (base sm_103 target OK)
// ---------------------------------------------------------------------------
__device__ __forceinline__ void mma_f16(float* c, const uint32_t* a, const uint32_t* b) {
    asm volatile(
        "mma.sync.aligned.m16n8k16.row.col.f32.f16.f16.f32 "
        "{%0,%1,%2,%3}, {%4,%5,%6,%7}, {%8,%9}, {%0,%1,%2,%3};"
        : "+f"(c[0]), "+f"(c[1]), "+f"(c[2]), "+f"(c[3])
        : "r"(a[0]), "r"(a[1]), "r"(a[2]), "r"(a[3]),
          "r"(b[0]), "r"(b[1]));
}

__device__ __forceinline__ uint32_t packh2(float a, float b) {
    __half2 h = __floats2half2_rn(a, b);
    return *(uint32_t*)&h;
}

__device__ __forceinline__ void cp_async16(uint32_t dst, const void* src) {
    asm volatile("cp.async.cg.shared.global [%0], [%1], 16;" :: "r"(dst), "l"(src));
}
__device__ __forceinline__ void cp_commit() {
    asm volatile("cp.async.commit_group;" ::: "memory");
}
__device__ __forceinline__ void cp_wait2() {
    asm volatile("cp.async.wait_group 2;" ::: "memory");
}

#define LDSM4(r0, r1, r2, r3, addr) \
    asm volatile("ldmatrix.sync.aligned.m8n8.x4.shared.b16 {%0,%1,%2,%3}, [%4];" \
                 : "=r"(r0), "=r"(r1), "=r"(r2), "=r"(r3) : "r"(addr))

#define LDSM4T(r0, r1, r2, r3, addr) \
    asm volatile("ldmatrix.sync.aligned.m8n8.x4.trans.shared.b16 {%0,%1,%2,%3}, [%4];" \
                 : "=r"(r0), "=r"(r1), "=r"(r2), "=r"(r3) : "r"(addr))

// 64B-row XOR swizzle (GEMM stages): 16B segment for (row, chunk c in 0..3)
__device__ __forceinline__ int phys16(int row, int c) {
    return (row >> 1) * 8 + ((((row & 1) << 2) | c) ^ ((row >> 1) & 3));
}
// 128B-row XOR swizzle (attention tiles): seg for (row, seg-col c in 0..7)
#define ATT_SEG(row, c) (((row) * 8) + ((c) ^ ((row) & 7)))

// ---------------------------------------------------------------------------
// Fused operand prep: x->fp16 + 4 weight transposes in ONE kernel (R14)
// ---------------------------------------------------------------------------
__device__ __forceinline__ void transpose_tile(const float* __restrict__ src,
                                               __half* __restrict__ dst,
                                               int R, int C, int bx, int by,
                                               float (*t)[33])
{
    const int tx = threadIdx.x & 31;
    const int ty = threadIdx.x >> 5;
    #pragma unroll
    for (int i = 0; i < 32; i += 8)
        t[ty + i][tx] = src[(size_t)(by + ty + i) * C + bx + tx];
    __syncthreads();
    #pragma unroll
    for (int i = 0; i < 32; i += 8)
        dst[(size_t)(bx + ty + i) * R + by + tx] = __float2half(t[tx][ty + i]);
}

__global__ __launch_bounds__(256)
void prep_k(const float* __restrict__ x,
            const float* __restrict__ w_qkv,
            const float* __restrict__ w_o,
            const float* __restrict__ w1,
            const float* __restrict__ w2)
{
    __shared__ float t[32][33];
    const int id = blockIdx.x;

    if (id < 4096) {
        uint32_t* d = (uint32_t*)g_x16;
        const int i = id * 256 + threadIdx.x;
        const float4 v = ((const float4*)x)[i];
        d[i * 2 + 0] = packh2(v.x, v.y);
        d[i * 2 + 1] = packh2(v.z, v.w);
    } else if (id < 7168) {
        const int b = id - 4096;
        transpose_tile(w_qkv, g_wqkvT16, D, 3 * D, (b % 96) * 32, (b / 96) * 32, t);
    } else if (id < 8192) {
        const int b = id - 7168;
        transpose_tile(w_o, g_woT16, D, D, (b % 32) * 32, (b / 32) * 32, t);
    } else if (id < 12288) {
        const int b = id - 8192;
        transpose_tile(w1, g_w1T16, D, FF, (b % 128) * 32, (b / 128) * 32, t);
    } else {
        const int b = id - 12288;
        transpose_tile(w2, g_w2T16, FF, D, (b % 32) * 32, (b / 32) * 32, t);
    }
}

// ---------------------------------------------------------------------------
// FP16 GEMM 128x128 (R10-validated, FROZEN): 8 warps 64x32, BK=32, 4 stages
// ---------------------------------------------------------------------------
#define STAGE_B 16384
#define GEMM_SMEM (4 * STAGE_B)   // 65536

__global__ __launch_bounds__(256)
void gemm_f16(int Aid, int Bid, const float* __restrict__ bias,
              int Cid, int outHalf, int M, int N, int K, int relu)
{
    extern __shared__ char smem[];
    const uint32_t smem_u = (uint32_t)__cvta_generic_to_shared(smem);

    const __half* A  = scratch_h(Aid);
    const __half* Bt = scratch_h(Bid);

    const int tid  = threadIdx.x;
    const int wid  = tid >> 5;
    const int lane = tid & 31;
    const int gid  = lane >> 2;
    const int tig  = lane & 3;
    const int warpM = (wid & 1) * 64;
    const int warpN = (wid >> 1) * 32;
    const int m0 = blockIdx.y * 128;
    const int n0 = blockIdx.x * 128;

    uint32_t ld_dst[4];
    const __half* ld_src[4];
    #pragma unroll
    for (int j = 0; j < 4; j++) {
        const int s   = j * 256 + tid;
        const int isB = s >= 512;
        const int ss  = s & 511;
        const int row = ss >> 2;
        const int c   = ss & 3;
        ld_dst[j] = (isB ? 8192u : 0u) + (uint32_t)phys16(row, c) * 16u;
        ld_src[j] = (isB ? Bt + (size_t)(n0 + row) * K
                         : A  + (size_t)(m0 + row) * K) + c * 8;
    }

    const int hi = lane >> 4;
    const int rr = (lane & 7) + ((lane >> 3) & 1) * 8;
    uint32_t a_off[2][4], b_off[2][2];
    {
        const int ra = warpM + rr;
        const int la = ra >> 1, xa = (ra & 1) << 2, sa = la & 3;
        const int rb = warpN + rr;
        const int lb = rb >> 1, xb = (rb & 1) << 2, sb = lb & 3;
        #pragma unroll
        for (int ks = 0; ks < 2; ks++) {
            const int c = 2 * ks + hi;
            #pragma unroll
            for (int mt = 0; mt < 4; mt++)
                a_off[ks][mt] = (uint32_t)(la * 8 + mt * 64 + ((xa | c) ^ sa)) * 16u;
            #pragma unroll
            for (int n2 = 0; n2 < 2; n2++)
                b_off[ks][n2] = 8192u + (uint32_t)(lb * 8 + n2 * 64 + ((xb | c) ^ sb)) * 16u;
        }
    }

    float acc[4][4][4];
    #pragma unroll
    for (int mt = 0; mt < 4; mt++)
        #pragma unroll
        for (int nt = 0; nt < 4; nt++)
            #pragma unroll
            for (int c = 0; c < 4; c++) acc[mt][nt][c] = 0.f;

    const int nk = K >> 5;

    for (int s = 0; s < 3; s++) {
        const uint32_t sb_ = smem_u + s * STAGE_B;
        #pragma unroll
        for (int j = 0; j < 4; j++)
            cp_async16(sb_ + ld_dst[j], ld_src[j] + s * 32);
        cp_commit();
    }

    for (int kc = 0; kc < nk; kc++) {
        cp_wait2();
        __syncthreads();

        if (kc + 3 < nk) {
            const uint32_t sb_ = smem_u + ((kc + 3) & 3) * STAGE_B;
            #pragma unroll
            for (int j = 0; j < 4; j++)
                cp_async16(sb_ + ld_dst[j], ld_src[j] + (kc + 3) * 32);
        }
        cp_commit();

        const uint32_t st = smem_u + (kc & 3) * STAGE_B;
        #pragma unroll
        for (int ks = 0; ks < 2; ks++) {
            uint32_t bfr[4][2];
            {
                uint32_t r0, r1, r2, r3;
                LDSM4(r0, r1, r2, r3, st + b_off[ks][0]);
                bfr[0][0] = r0; bfr[1][0] = r1; bfr[0][1] = r2; bfr[1][1] = r3;
            }
            {
                uint32_t r0, r1, r2, r3;
                LDSM4(r0, r1, r2, r3, st + b_off[ks][1]);
                bfr[2][0] = r0; bfr[3][0] = r1; bfr[2][1] = r2; bfr[3][1] = r3;
            }
            #pragma unroll
            for (int mt = 0; mt < 4; mt++) {
                uint32_t af[4];
                LDSM4(af[0], af[1], af[2], af[3], st + a_off[ks][mt]);
                #pragma unroll
                for (int nt = 0; nt < 4; nt++)
                    mma_f16(acc[mt][nt], af, bfr[nt]);
            }
        }
    }

    if (outHalf) {
        __half* C = scratch_h(Cid);
        #pragma unroll
        for (int nt = 0; nt < 4; nt++) {
            const int n = n0 + warpN + nt * 8 + 2 * tig;
            const float b0 = bias[n], b1 = bias[n + 1];
            #pragma unroll
            for (int mt = 0; mt < 4; mt++) {
                const int m = m0 + warpM + mt * 16 + gid;
                float v0 = acc[mt][nt][0] + b0, v1 = acc[mt][nt][1] + b1;
                float v2 = acc[mt][nt][2] + b0, v3 = acc[mt][nt][3] + b1;
                if (relu) {
                    v0 = fmaxf(v0, 0.f); v1 = fmaxf(v1, 0.f);
                    v2 = fmaxf(v2, 0.f); v3 = fmaxf(v3, 0.f);
                }
                *(uint32_t*)&C[(size_t)m * N + n]       = packh2(v0, v1);
                *(uint32_t*)&C[(size_t)(m + 8) * N + n] = packh2(v2, v3);
            }
        }
    } else {
        float* C = scratch(Cid);
        #pragma unroll
        for (int nt = 0; nt < 4; nt++) {
            const int n = n0 + warpN + nt * 8 + 2 * tig;
            const float b0 = bias[n], b1 = bias[n + 1];
            #pragma unroll
            for (int mt = 0; mt < 4; mt++) {
                const int m = m0 + warpM + mt * 16 + gid;
                float2 v0 = make_float2(acc[mt][nt][0] + b0, acc[mt][nt][1] + b1);
                float2 v1 = make_float2(acc[mt][nt][2] + b0, acc[mt][nt][3] + b1);
                if (relu) {
                    v0.x = fmaxf(v0.x, 0.f); v0.y = fmaxf(v0.y, 0.f);
                    v1.x = fmaxf(v1.x, 0.f); v1.y = fmaxf(v1.y, 0.f);
                }
                *(float2*)&C[(size_t)m * N + n]       = v0;
                *(float2*)&C[(size_t)(m + 8) * N + n] = v1;
            }
        }
    }
}

// ---------------------------------------------------------------------------
// FP16 flash attention (R10-validated, FROZEN)
// ---------------------------------------------------------------------------
__global__ __launch_bounds__(128)
void attn_f16()
{
    __shared__ __align__(16) uint8_t sm[16384];
    const uint32_t su = (uint32_t)__cvta_generic_to_shared(sm);

    const int nB  = blockIdx.z;
    const int h   = blockIdx.y;
    const int q0  = blockIdx.x * 128;
    const int tid = threadIdx.x;
    const int wid = tid >> 5;
    const int lane = tid & 31;
    const int gid  = lane >> 2;
    const int tig  = lane & 3;
    const int warpM = wid * 32;
    const int rr = (lane & 7) + ((lane >> 3) & 1) * 8;
    const int hi = lane >> 4;
    const float qscale = 0.125f * 1.44269504f;

    #pragma unroll
    for (int t = 0; t < 8; t++) {
        const int i = t * 128 + tid;
        const int row = i >> 3, c = i & 7;
        const __half* src = g_qkv16 + (size_t)(nB * LQ + q0 + row) * (3 * D) + h * HD + c * 8;
        *(uint4*)(sm + ATT_SEG(row, c) * 16) = *(const uint4*)src;
    }
    __syncthreads();

    uint32_t qf[2][4][4];
    #pragma unroll
    for (int mt = 0; mt < 2; mt++)
        #pragma unroll
        for (int kc = 0; kc < 4; kc++) {
            const int row = warpM + mt * 16 + rr;
            LDSM4(qf[mt][kc][0], qf[mt][kc][1], qf[mt][kc][2], qf[mt][kc][3],
                  su + ATT_SEG(row, 2 * kc + hi) * 16);
        }
    __syncthreads();

    float oac[2][8][4];
    #pragma unroll
    for (int mt = 0; mt < 2; mt++)
        #pragma unroll
        for (int nt = 0; nt < 8; nt++)
            #pragma unroll
            for (int c = 0; c < 4; c++) oac[mt][nt][c] = 0.f;
    float mrow[2][2] = {{-1e30f, -1e30f}, {-1e30f, -1e30f}};
    float lrow[2][2] = {{0.f, 0.f}, {0.f, 0.f}};

    for (int kt = 0; kt < LQ / 64; kt++) {
        #pragma unroll
        for (int t = 0; t < 4; t++) {
            const int i = t * 128 + tid;
            const int row = i >> 3, c = i & 7;
            const __half* base = g_qkv16 + (size_t)(nB * LQ + kt * 64 + row) * (3 * D) + h * HD + c * 8;
            *(uint4*)(sm + ATT_SEG(row, c) * 16)        = *(const uint4*)(base + D);
            *(uint4*)(sm + 8192 + ATT_SEG(row, c) * 16) = *(const uint4*)(base + 2 * D);
        }
        __syncthreads();

        float sacc[2][8][4];
        #pragma unroll
        for (int mt = 0; mt < 2; mt++)
            #pragma unroll
            for (int nt = 0; nt < 8; nt++)
                #pragma unroll
                for (int c = 0; c < 4; c++) sacc[mt][nt][c] = 0.f;

        #pragma unroll
        for (int ks = 0; ks < 4; ks++) {
            uint32_t bfr[8][2];
            #pragma unroll
            for (int np = 0; np < 4; np++) {
                uint32_t r0, r1, r2, r3;
                LDSM4(r0, r1, r2, r3, su + ATT_SEG(np * 16 + rr, 2 * ks + hi) * 16);
                bfr[2 * np][0] = r0; bfr[2 * np + 1][0] = r1;
                bfr[2 * np][1] = r2; bfr[2 * np + 1][1] = r3;
            }
            #pragma unroll
            for (int mt = 0; mt < 2; mt++)
                #pragma unroll
                for (int nt = 0; nt < 8; nt++)
                    mma_f16(sacc[mt][nt], qf[mt][ks], bfr[nt]);
        }

        #pragma unroll
        for (int mt = 0; mt < 2; mt++) {
            #pragma unroll
            for (int nt = 0; nt < 8; nt++) {
                sacc[mt][nt][0] *= qscale; sacc[mt][nt][1] *= qscale;
                sacc[mt][nt][2] *= qscale; sacc[mt][nt][3] *= qscale;
            }
            float mx0 = -1e30f, mx1 = -1e30f;
            #pragma unroll
            for (int nt = 0; nt < 8; nt++) {
                mx0 = fmaxf(mx0, fmaxf(sacc[mt][nt][0], sacc[mt][nt][1]));
                mx1 = fmaxf(mx1, fmaxf(sacc[mt][nt][2], sacc[mt][nt][3]));
            }
            mx0 = fmaxf(mx0, __shfl_xor_sync(0xFFFFFFFFu, mx0, 1));
            mx0 = fmaxf(mx0, __shfl_xor_sync(0xFFFFFFFFu, mx0, 2));
            mx1 = fmaxf(mx1, __shfl_xor_sync(0xFFFFFFFFu, mx1, 1));
            mx1 = fmaxf(mx1, __shfl_xor_sync(0xFFFFFFFFu, mx1, 2));

            const float mn0 = fmaxf(mrow[mt][0], mx0);
            const float mn1 = fmaxf(mrow[mt][1], mx1);
            const float cr0 = exp2f(mrow[mt][0] - mn0);
            const float cr1 = exp2f(mrow[mt][1] - mn1);
            mrow[mt][0] = mn0;
            mrow[mt][1] = mn1;

            float ls0 = 0.f, ls1 = 0.f;
            #pragma unroll
            for (int nt = 0; nt < 8; nt++) {
                sacc[mt][nt][0] = exp2f(sacc[mt][nt][0] - mn0);
                sacc[mt][nt][1] = exp2f(sacc[mt][nt][1] - mn0);
                sacc[mt][nt][2] = exp2f(sacc[mt][nt][2] - mn1);
                sacc[mt][nt][3] = exp2f(sacc[mt][nt][3] - mn1);
                ls0 += sacc[mt][nt][0] + sacc[mt][nt][1];
                ls1 += sacc[mt][nt][2] + sacc[mt][nt][3];
            }
            ls0 += __shfl_xor_sync(0xFFFFFFFFu, ls0, 1);
            ls0 += __shfl_xor_sync(0xFFFFFFFFu, ls0, 2);
            ls1 += __shfl_xor_sync(0xFFFFFFFFu, ls1, 1);
            ls1 += __shfl_xor_sync(0xFFFFFFFFu, ls1, 2);
            lrow[mt][0] = lrow[mt][0] * cr0 + ls0;
            lrow[mt][1] = lrow[mt][1] * cr1 + ls1;

            #pragma unroll
            for (int nt = 0; nt < 8; nt++) {
                oac[mt][nt][0] *= cr0; oac[mt][nt][1] *= cr0;
                oac[mt][nt][2] *= cr1; oac[mt][nt][3] *= cr1;
            }
        }

        #pragma unroll
        for (int kc = 0; kc < 4; kc++) {
            uint32_t vb[8][2];
            #pragma unroll
            for (int dp = 0; dp < 4; dp++) {
                uint32_t r0, r1, r2, r3;
                LDSM4T(r0, r1, r2, r3, su + 8192 + ATT_SEG(kc * 16 + rr, 2 * dp + hi) * 16);
                vb[2 * dp][0] = r0; vb[2 * dp][1] = r1;
                vb[2 * dp + 1][0] = r2; vb[2 * dp + 1][1] = r3;
            }
            uint32_t pa[2][4];
            #pragma unroll
            for (int mt = 0; mt < 2; mt++) {
                pa[mt][0] = packh2(sacc[mt][2 * kc][0],     sacc[mt][2 * kc][1]);
                pa[mt][1] = packh2(sacc[mt][2 * kc][2],     sacc[mt][2 * kc][3]);
                pa[mt][2] = packh2(sacc[mt][2 * kc + 1][0], sacc[mt][2 * kc + 1][1]);
                pa[mt][3] = packh2(sacc[mt][2 * kc + 1][2], sacc[mt][2 * kc + 1][3]);
            }
            #pragma unroll
            for (int mt = 0; mt < 2; mt++)
                #pragma unroll
                for (int ntd = 0; ntd < 8; ntd++)
                    mma_f16(oac[mt][ntd], pa[mt], vb[ntd]);
        }
        __syncthreads();
    }

    #pragma unroll
    for (int mt = 0; mt < 2; mt++) {
        const float inv0 = 1.f / lrow[mt][0];
        const float inv1 = 1.f / lrow[mt][1];
        const int grow = nB * LQ + q0 + warpM + mt * 16 + gid;
        #pragma unroll
        for (int ntd = 0; ntd < 8; ntd++) {
            const int col = h * HD + ntd * 8 + 2 * tig;
            *(uint32_t*)&g_attn16[(size_t)grow * D + col] =
                packh2(oac[mt][ntd][0] * inv0, oac[mt][ntd][1] * inv0);
            *(uint32_t*)&g_attn16[(size_t)(grow + 8) * D + col] =
                packh2(oac[mt][ntd][2] * inv1, oac[mt][ntd][3] * inv1);
        }
    }
}

// ---------------------------------------------------------------------------
// Residual add + LayerNorm, mixed dtype in/out.
// a: fp16 scratch (aHid). b: fp16 scratch (bHid) OR external fp32 (bF32).
// out: external fp32 (outF32) and/or fp16 scratch (outHid).
// ---------------------------------------------------------------------------
__global__ __launch_bounds__(256)
void add_ln_kernel(int aHid, int bHid, const float* __restrict__ bF32,
                   const float* __restrict__ gamma,
                   const float* __restrict__ beta,
                   float* __restrict__ outF32, int outHid)
{
    const __half* a = scratch_h(aHid);
    const __half* bh = (bHid >= 0) ? scratch_h(bHid) : (const __half*)0;

    const int row = blockIdx.x;
    const int tid = threadIdx.x;
    const size_t base = (size_t)row * D;

    float v[4];
    float s = 0.f, s2 = 0.f;
    #pragma unroll
    for (int i = 0; i < 4; i++) {
        int col = tid + i * 256;
        float av = __half2float(a[base + col]);
        float bv = bh ? __half2float(bh[base + col]) : bF32[base + col];
        float x = av + bv;
        v[i] = x;
        s  += x;
        s2 += x * x;
    }
    #pragma unroll
    for (int off = 16; off; off >>= 1) {
        s  += __shfl_xor_sync(0xFFFFFFFFu, s,  off);
        s2 += __shfl_xor_sync(0xFFFFFFFFu, s2, off);
    }
    __shared__ float rs[8], rs2[8];
    const int warp = tid >> 5, lane = tid & 31;
    if (lane == 0) { rs[warp] = s; rs2[warp] = s2; }
    __syncthreads();
    float ts = 0.f, ts2 = 0.f;
    #pragma unroll
    for (int w = 0; w < 8; w++) { ts += rs[w]; ts2 += rs2[w]; }

    const float mu  = ts * (1.f / D);
    const float var = ts2 * (1.f / D) - mu * mu;
    const float inv = rsqrtf(var + EPS);

    __half* ho = (outHid >= 0) ? scratch_h(outHid) : (__half*)0;
    #pragma unroll
    for (int i = 0; i < 4; i++) {
        int col = tid + i * 256;
        float r = (v[i] - mu) * inv * gamma[col] + beta[col];
        if (outF32) outF32[base + col] = r;
        if (ho)     ho[base + col] = __float2half(r);
    }
}

// ---------------------------------------------------------------------------
// Launch
// ---------------------------------------------------------------------------
extern "C" void kernel_launch(void* const* d_in, const int* in_sizes, int n_in,
                              void* d_out, int out_size)
{
    const float* x     = (const float*)d_in[0];
    const float* w_qkv = (const float*)d_in[1];
    const float* b_qkv = (const float*)d_in[2];
    const float* w_o   = (const float*)d_in[3];
    const float* b_o   = (const float*)d_in[4];
    const float* g1    = (const float*)d_in[5];
    const float* be1   = (const float*)d_in[6];
    const float* w1    = (const float*)d_in[7];
    const float* b1    = (const float*)d_in[8];
    const float* w2    = (const float*)d_in[9];
    const float* b2    = (const float*)d_in[10];
    const float* g2    = (const float*)d_in[11];
    const float* be2   = (const float*)d_in[12];
    float* out = (float*)d_out;

    cudaFuncSetAttribute(gemm_f16,
                         cudaFuncAttributeMaxDynamicSharedMemorySize, GEMM_SMEM);

    // 0. fused operand prep (cvt x + 4 transposes)
    prep_k<<<16384, 256>>>(x, w_qkv, w_o, w1, w2);

    // 1. QKV: x16 (h0) @ wqkvT16 -> g_qkv16 (fp16)
    gemm_f16<<<dim3(3 * D / 128, MROWS / 128), 256, GEMM_SMEM>>>(
        0, 4, b_qkv, 8, 1, MROWS, 3 * D, D, 0);

    // 2. attention -> g_attn16 (h1)
    attn_f16<<<dim3(LQ / 128, H_, NB), 128>>>();

    // 3. proj: attn16 (h1) @ woT16 -> proj16 (h0, reusing g_x16)
    gemm_f16<<<dim3(D / 128, MROWS / 128), 256, GEMM_SMEM>>>(
        1, 5, b_o, 0, 1, MROWS, D, D, 0);

    // 4. h = LN(proj16 + x) -> h16 (h2) only
    add_ln_kernel<<<MROWS, 256>>>(0, -1, x, g1, be1, nullptr, 2);

    // 5. FF1: h16 (h2) @ w1T16 + ReLU -> g_ff116 (h3)
    gemm_f16<<<dim3(FF / 128, MROWS / 128), 256, GEMM_SMEM>>>(
        2, 6, b1, 3, 1, MROWS, FF, D, 1);

    // 6. FF2: ff116 (h3) @ w2T16 -> ff216 (h1, reusing g_attn16)
    gemm_f16<<<dim3(D / 128, MROWS / 128), 256, GEMM_SMEM>>>(
        3, 7, b2, 1, 1, MROWS, D, FF, 0);

    // 7. out = LN(h16 + ff216) -> fp32 output
    add_ln_kernel<<<MROWS, 256>>>(2, 1, nullptr, g2, be2, out, -1);
}